// round 3
// baseline (speedup 1.0000x reference)
#include <cuda_runtime.h>
#include <math.h>

// Biquad lowpass (fs=44100, fc=10000, Q=0.707) as a truncated-FIR convolution.
// Pole magnitude 0.4203 -> truncation error at K=12 taps ~ 0.4203^12 ~ 3e-5,
// well below the 1e-3 threshold.
// R3: 16 outputs/thread, K=12 -> 28-float register window (7x float4).
// L1 traffic drops to ~11 B/output (was 16); kernel should go DRAM-bound.

#define K_TAPS 12
#define OUTS   16
#define WIN    (K_TAPS + OUTS)  // 28 floats = 7 float4
#define T_LEN  160000

struct FirParams {
    float h[K_TAPS];
};

__global__ __launch_bounds__(256) void lowpass_fir_kernel(
    const float* __restrict__ clip,
    float* __restrict__ out,
    FirParams p)
{
    const int t = (blockIdx.x * blockDim.x + threadIdx.x) * OUTS;
    if (t >= T_LEN) return;

    const size_t row = (size_t)blockIdx.y * T_LEN;
    const float* __restrict__ x = clip + row;

    float w[WIN];

    if (t >= K_TAPS) {
        // Fast path: in-bounds and 16B-aligned (t - 12 is a multiple of 4).
        const float4* __restrict__ p4 = reinterpret_cast<const float4*>(x + t - K_TAPS);
        #pragma unroll
        for (int i = 0; i < WIN / 4; i++) {
            float4 v = p4[i];
            w[4 * i + 0] = v.x;
            w[4 * i + 1] = v.y;
            w[4 * i + 2] = v.z;
            w[4 * i + 3] = v.w;
        }
    } else {
        // Left edge (first thread of each row): zero-pad x[t'] for t' < 0.
        #pragma unroll
        for (int i = 0; i < WIN; i++) {
            int idx = t - K_TAPS + i;
            w[i] = (idx >= 0) ? x[idx] : 0.0f;
        }
    }

    float y[OUTS];
    #pragma unroll
    for (int j = 0; j < OUTS; j++) y[j] = 0.0f;

    #pragma unroll
    for (int k = 0; k < K_TAPS; k++) {
        const float hk = p.h[k];
        // y_{t+j} = sum_k h_k * x[t+j-k]; w[i] = x[t - K + i] -> x[t+j-k] = w[K + j - k]
        #pragma unroll
        for (int j = 0; j < OUTS; j++)
            y[j] = fmaf(hk, w[K_TAPS + j - k], y[j]);
    }

    float4* __restrict__ o4 = reinterpret_cast<float4*>(out + row + t);
    #pragma unroll
    for (int j = 0; j < OUTS / 4; j++) {
        float4 r;
        r.x = y[4 * j + 0];
        r.y = y[4 * j + 1];
        r.z = y[4 * j + 2];
        r.w = y[4 * j + 3];
        o4[j] = r;
    }
}

extern "C" void kernel_launch(void* const* d_in, const int* in_sizes, int n_in,
                              void* d_out, int out_size)
{
    const float* clip = (const float*)d_in[0];
    float* out = (float*)d_out;

    const int total = in_sizes[0];
    const int batch = total / T_LEN;   // 128

    // Coefficients in double, exactly as the reference computes them.
    const double fs = 44100.0, fc = 10000.0, q = 0.707;
    const double w0 = 2.0 * M_PI * fc / fs;
    const double alpha = sin(w0) / (2.0 * q);
    const double cw = cos(w0);
    const double a0 = 1.0 + alpha;
    const double b0 = ((1.0 - cw) / 2.0) / a0;
    const double b1 = (1.0 - cw) / a0;
    const double b2 = b0;
    const double a1 = (-2.0 * cw) / a0;
    const double a2 = (1.0 - alpha) / a0;

    // Impulse response of the biquad (truncated to K_TAPS).
    double hd[K_TAPS];
    hd[0] = b0;
    hd[1] = b1 - a1 * hd[0];
    hd[2] = b2 - a1 * hd[1] - a2 * hd[0];
    for (int k = 3; k < K_TAPS; k++)
        hd[k] = -a1 * hd[k - 1] - a2 * hd[k - 2];

    FirParams p;
    for (int k = 0; k < K_TAPS; k++) p.h[k] = (float)hd[k];

    const int threads = 256;
    const int outs_per_block = threads * OUTS;                          // 4096
    const int blocks_x = (T_LEN + outs_per_block - 1) / outs_per_block; // 40
    dim3 grid(blocks_x, batch);

    lowpass_fir_kernel<<<grid, threads>>>(clip, out, p);
}

// round 4
// speedup vs baseline: 1.0010x; 1.0010x over previous
#include <cuda_runtime.h>
#include <math.h>

// Biquad lowpass (fs=44100, fc=10000, Q=0.707) as truncated-FIR (K=12,
// pole mag 0.4203 -> trunc err ~3e-5 << 1e-3).
// R4: coalesced loads + warp-shuffle halo. Lane l loads float4 at seg+l*4
// (perfect coalescing, 4 wavefronts/512B); the 11 preceding samples come from
// shfl_up of neighbor lanes' float4s; lanes 0-2 patch the out-of-warp halo
// with a few extra loads (1-2 cache lines). 2 segments/warp for MLP.

#define K_TAPS 12
#define SEG    128          // outputs per warp per segment
#define SEGS_PER_WARP 2
#define WARPS  8
#define T_LEN  160000

struct FirParams {
    float h[K_TAPS];
};

__device__ __forceinline__ float4 ld4_or_zero(const float* __restrict__ x, int idx) {
    if (idx >= 0)
        return *reinterpret_cast<const float4*>(x + idx);
    float4 z; z.x = z.y = z.z = z.w = 0.f;
    return z;
}

__device__ __forceinline__ float4 shfl_up4(float4 v, int delta) {
    float4 r;
    r.x = __shfl_up_sync(0xFFFFFFFFu, v.x, delta);
    r.y = __shfl_up_sync(0xFFFFFFFFu, v.y, delta);
    r.z = __shfl_up_sync(0xFFFFFFFFu, v.z, delta);
    r.w = __shfl_up_sync(0xFFFFFFFFu, v.w, delta);
    return r;
}

__global__ __launch_bounds__(WARPS * 32) void lowpass_fir_kernel(
    const float* __restrict__ clip,
    float* __restrict__ out,
    FirParams p)
{
    const int warp = threadIdx.x >> 5;
    const int lane = threadIdx.x & 31;

    const size_t row = (size_t)blockIdx.y * T_LEN;
    const float* __restrict__ x = clip + row;
    float* __restrict__ o = out + row;

    const int seg_base = (blockIdx.x * WARPS + warp) * SEGS_PER_WARP;

    #pragma unroll
    for (int si = 0; si < SEGS_PER_WARP; si++) {
        const int s = (seg_base + si) * SEG;
        if (s >= T_LEN) break;

        const int t = s + lane * 4;   // this lane's first output

        // Coalesced main load: lane-contiguous float4s covering [s, s+512).
        float4 v = *reinterpret_cast<const float4*>(x + t);

        // Previous 12 samples for this lane come from lanes l-1, l-2, l-3.
        float4 p1 = shfl_up4(v, 1);   // x4[t-4]
        float4 p2 = shfl_up4(v, 2);   // x4[t-8]
        float4 p3 = shfl_up4(v, 3);   // x4[t-12]

        // Halo fixup for lanes 0-2 (data from before this warp's segment).
        if (lane == 0) {
            p1 = ld4_or_zero(x, s - 4);
            p2 = ld4_or_zero(x, s - 8);
            p3 = ld4_or_zero(x, s - 12);
        } else if (lane == 1) {
            p2 = ld4_or_zero(x, s - 4);
            p3 = ld4_or_zero(x, s - 8);
        } else if (lane == 2) {
            p3 = ld4_or_zero(x, s - 4);
        }

        // Window w[i] = x[t - 12 + i], i = 0..15 (w[0] unused for K=12).
        float w[16];
        w[0]  = p3.x; w[1]  = p3.y; w[2]  = p3.z; w[3]  = p3.w;
        w[4]  = p2.x; w[5]  = p2.y; w[6]  = p2.z; w[7]  = p2.w;
        w[8]  = p1.x; w[9]  = p1.y; w[10] = p1.z; w[11] = p1.w;
        w[12] = v.x;  w[13] = v.y;  w[14] = v.z;  w[15] = v.w;

        float y0 = 0.f, y1 = 0.f, y2 = 0.f, y3 = 0.f;
        #pragma unroll
        for (int k = 0; k < K_TAPS; k++) {
            const float hk = p.h[k];
            y0 = fmaf(hk, w[12 + 0 - k], y0);
            y1 = fmaf(hk, w[12 + 1 - k], y1);
            y2 = fmaf(hk, w[12 + 2 - k], y2);
            y3 = fmaf(hk, w[12 + 3 - k], y3);
        }

        float4 r;
        r.x = y0; r.y = y1; r.z = y2; r.w = y3;
        *reinterpret_cast<float4*>(o + t) = r;   // coalesced store
    }
}

extern "C" void kernel_launch(void* const* d_in, const int* in_sizes, int n_in,
                              void* d_out, int out_size)
{
    const float* clip = (const float*)d_in[0];
    float* out = (float*)d_out;

    const int total = in_sizes[0];
    const int batch = total / T_LEN;   // 128

    // Coefficients in double, exactly as the reference computes them.
    const double fs = 44100.0, fc = 10000.0, q = 0.707;
    const double w0 = 2.0 * M_PI * fc / fs;
    const double alpha = sin(w0) / (2.0 * q);
    const double cw = cos(w0);
    const double a0 = 1.0 + alpha;
    const double b0 = ((1.0 - cw) / 2.0) / a0;
    const double b1 = (1.0 - cw) / a0;
    const double b2 = b0;
    const double a1 = (-2.0 * cw) / a0;
    const double a2 = (1.0 - alpha) / a0;

    // Impulse response of the biquad (truncated to K_TAPS).
    double hd[K_TAPS];
    hd[0] = b0;
    hd[1] = b1 - a1 * hd[0];
    hd[2] = b2 - a1 * hd[1] - a2 * hd[0];
    for (int k = 3; k < K_TAPS; k++)
        hd[k] = -a1 * hd[k - 1] - a2 * hd[k - 2];

    FirParams p;
    for (int k = 0; k < K_TAPS; k++) p.h[k] = (float)hd[k];

    const int segments = T_LEN / SEG;                       // 1250
    const int segs_per_block = WARPS * SEGS_PER_WARP;       // 16
    const int blocks_x = (segments + segs_per_block - 1) / segs_per_block;  // 79
    dim3 grid(blocks_x, batch);

    lowpass_fir_kernel<<<grid, WARPS * 32>>>(clip, out, p);
}

// round 5
// speedup vs baseline: 1.0612x; 1.0602x over previous
#include <cuda_runtime.h>
#include <math.h>

// Biquad lowpass (fs=44100, fc=10000, Q=0.707) as truncated-FIR (K=12,
// pole mag 0.4203 -> trunc err ~3.8e-5 << 1e-3).
// R5: smem-staged tile. Block loads 4096 outputs (+16 halo floats) coalesced
// as float4 (front-batched, high MLP), then each thread computes 4 outputs per
// iteration reading 4 consecutive float4 from smem at 16B lane stride
// (conflict-free LDS.128). No shuffles, no hot-path branches.

#define K_TAPS   12
#define T_LEN    160000
#define THREADS  256
#define OUTS     4
#define ITERS    4
#define TILE     (THREADS * OUTS * ITERS)   // 4096 outputs per block
#define HALO     16                         // >= K_TAPS, 16B-aligned
#define SMEM_F   (TILE + HALO)              // 4112 floats
#define SMEM_V4  (SMEM_F / 4)               // 1028 float4

struct FirParams {
    float h[K_TAPS];
};

__global__ __launch_bounds__(THREADS) void lowpass_fir_kernel(
    const float* __restrict__ clip,
    float* __restrict__ out,
    FirParams p)
{
    __shared__ float4 tile4[SMEM_V4];

    const int tid = threadIdx.x;
    const size_t row = (size_t)blockIdx.y * T_LEN;
    const float* __restrict__ x = clip + row;
    float* __restrict__ o = out + row;

    const int g = blockIdx.x * TILE;        // first output of this tile
    // smem[j] = x[g - HALO + 4*j .. +3]

    // ---- Cooperative coalesced load (guarded at row edges) ----
    #pragma unroll
    for (int i = 0; i < (SMEM_V4 + THREADS - 1) / THREADS; i++) {
        const int v = i * THREADS + tid;
        if (v < SMEM_V4) {
            const int base = g - HALO + 4 * v;   // multiple of 4
            float4 val;
            if (base >= 0 && base < T_LEN) {
                val = *reinterpret_cast<const float4*>(x + base);
            } else {
                val.x = val.y = val.z = val.w = 0.0f;
            }
            tile4[v] = val;
        }
    }
    __syncthreads();

    const float* __restrict__ sm = reinterpret_cast<const float*>(tile4);

    #pragma unroll
    for (int it = 0; it < ITERS; it++) {
        const int ofs = it * (THREADS * OUTS) + tid * OUTS;  // local output idx
        const int t = g + ofs;
        if (t >= T_LEN) break;

        // Window w[i] = x[t - 12 + i] = sm[ofs + 4 + i], i = 0..15.
        // ofs + 4 is a multiple of 4 -> 4 conflict-free LDS.128.
        const float4* __restrict__ w4 = reinterpret_cast<const float4*>(sm + ofs + 4);
        float w[16];
        #pragma unroll
        for (int i = 0; i < 4; i++) {
            float4 v = w4[i];
            w[4 * i + 0] = v.x;
            w[4 * i + 1] = v.y;
            w[4 * i + 2] = v.z;
            w[4 * i + 3] = v.w;
        }

        float y0 = 0.f, y1 = 0.f, y2 = 0.f, y3 = 0.f;
        #pragma unroll
        for (int k = 0; k < K_TAPS; k++) {
            const float hk = p.h[k];
            y0 = fmaf(hk, w[12 + 0 - k], y0);
            y1 = fmaf(hk, w[12 + 1 - k], y1);
            y2 = fmaf(hk, w[12 + 2 - k], y2);
            y3 = fmaf(hk, w[12 + 3 - k], y3);
        }

        float4 r;
        r.x = y0; r.y = y1; r.z = y2; r.w = y3;
        *reinterpret_cast<float4*>(o + t) = r;   // coalesced store
    }
}

extern "C" void kernel_launch(void* const* d_in, const int* in_sizes, int n_in,
                              void* d_out, int out_size)
{
    const float* clip = (const float*)d_in[0];
    float* out = (float*)d_out;

    const int total = in_sizes[0];
    const int batch = total / T_LEN;   // 128

    // Coefficients in double, exactly as the reference computes them.
    const double fs = 44100.0, fc = 10000.0, q = 0.707;
    const double w0 = 2.0 * M_PI * fc / fs;
    const double alpha = sin(w0) / (2.0 * q);
    const double cw = cos(w0);
    const double a0 = 1.0 + alpha;
    const double b0 = ((1.0 - cw) / 2.0) / a0;
    const double b1 = (1.0 - cw) / a0;
    const double b2 = b0;
    const double a1 = (-2.0 * cw) / a0;
    const double a2 = (1.0 - alpha) / a0;

    // Impulse response of the biquad (truncated to K_TAPS).
    double hd[K_TAPS];
    hd[0] = b0;
    hd[1] = b1 - a1 * hd[0];
    hd[2] = b2 - a1 * hd[1] - a2 * hd[0];
    for (int k = 3; k < K_TAPS; k++)
        hd[k] = -a1 * hd[k - 1] - a2 * hd[k - 2];

    FirParams p;
    for (int k = 0; k < K_TAPS; k++) p.h[k] = (float)hd[k];

    const int blocks_x = (T_LEN + TILE - 1) / TILE;   // 40
    dim3 grid(blocks_x, batch);

    lowpass_fir_kernel<<<grid, THREADS>>>(clip, out, p);
}